// round 3
// baseline (speedup 1.0000x reference)
#include <cuda_runtime.h>
#include <math.h>

#define BATCH 512
#define NNODE 513
#define DIM   256
#define NH    8
#define HDIM  32
#define TSTEPS 128
#define EWD   512          // U+1
#define NEGV  -1000000000.0f
#define INV_HD 0.176776695296636893f   // 1/sqrt(32)
#define INV_D  0.0625f                 // 1/sqrt(256)

// ---------------- static device scratch (no allocations allowed) ----------------
static __device__ float d_K[(size_t)BATCH * NH * NNODE * HDIM];   // (b,h,n,d)
static __device__ float d_V[(size_t)BATCH * NH * NNODE * HDIM];   // (b,h,n,d)
static __device__ float d_L[(size_t)BATCH * NNODE * DIM];         // (b,n,d)
static __device__ float d_fixed[BATCH * DIM];
static __device__ float d_ctx[BATCH * DIM];
static __device__ float d_q[BATCH * DIM];
static __device__ float d_heads[BATCH * DIM];
static __device__ float d_glimpse[BATCH * DIM];
static __device__ unsigned char d_mask[BATCH * NNODE];
static __device__ int d_sel[BATCH];

// 10*tanh(x) built from expf so --use_fast_math's __tanhf (2^-11 err) can't
// perturb the argmax chain.
__device__ __forceinline__ float tanh10(float x) {
  float ax = fabsf(x);
  float t = expf(-2.0f * ax);          // underflows to 0 for large ax -> r=1
  float r = (1.0f - t) / (1.0f + t);
  return copysignf(10.0f * r, x);
}

// ---------------- precompute: graph mean -> fixed_ctx; init state ----------------
__global__ void k_precompute_fixed(const float* __restrict__ ne,
                                   const float* __restrict__ w_fc,
                                   const float* __restrict__ b_fc) {
  int b = blockIdx.x, tid = threadIdx.x;         // 512 blocks x 256 threads
  __shared__ float mean[DIM];
  const float* base = ne + (size_t)b * NNODE * DIM;
  float acc = 0.f;
  for (int n = 0; n < NNODE; ++n) acc += base[(size_t)n * DIM + tid];
  mean[tid] = acc / (float)NNODE;
  __syncthreads();
  float o = b_fc[tid];
  for (int d = 0; d < DIM; ++d) o += mean[d] * w_fc[d * DIM + tid];
  d_fixed[b * DIM + tid] = o;
  d_ctx[b * DIM + tid] = 0.f;
  for (int i = tid; i < NNODE; i += 256) d_mask[(size_t)b * NNODE + i] = 0;
}

// ---------------- precompute: KVL = node_embeds @ w_kvl + b, scattered ----------------
// M = BATCH*NNODE = 262656, K = 256, N = 768.  64x64 tiles, BK=16, 4x4 per thread.
__global__ void k_kvl(const float* __restrict__ ne,
                      const float* __restrict__ w,
                      const float* __restrict__ bias) {
  __shared__ float As[16][72];   // [k][m], padded row (288B, 16B-aligned rows)
  __shared__ float Bs[16][64];   // [k][n]
  int tid = threadIdx.x;
  int tx = tid & 15, ty = tid >> 4;
  int row0 = blockIdx.x * 64;
  int col0 = blockIdx.y * 64;
  int ar = tid >> 2, ac4 = tid & 3;     // A loader: row, float4-col
  int br = tid >> 4, bc4 = tid & 15;    // B loader
  float acc[4][4];
#pragma unroll
  for (int i = 0; i < 4; i++)
#pragma unroll
    for (int j = 0; j < 4; j++) acc[i][j] = 0.f;

  for (int k0 = 0; k0 < DIM; k0 += 16) {
    float4 av = *(const float4*)&ne[(size_t)(row0 + ar) * DIM + k0 + ac4 * 4];
    As[ac4 * 4 + 0][ar] = av.x;
    As[ac4 * 4 + 1][ar] = av.y;
    As[ac4 * 4 + 2][ar] = av.z;
    As[ac4 * 4 + 3][ar] = av.w;
    *(float4*)&Bs[br][bc4 * 4] =
        *(const float4*)&w[(size_t)(k0 + br) * 768 + col0 + bc4 * 4];
    __syncthreads();
#pragma unroll
    for (int k = 0; k < 16; k++) {
      float4 a = *(const float4*)&As[k][ty * 4];
      float4 bv = *(const float4*)&Bs[k][tx * 4];
      float am[4] = {a.x, a.y, a.z, a.w};
      float bm[4] = {bv.x, bv.y, bv.z, bv.w};
#pragma unroll
      for (int i = 0; i < 4; i++)
#pragma unroll
        for (int j = 0; j < 4; j++) acc[i][j] += am[i] * bm[j];
    }
    __syncthreads();
  }
#pragma unroll
  for (int i = 0; i < 4; i++) {
    int m = row0 + ty * 4 + i;
    int bb = m / NNODE;
    int n = m - bb * NNODE;
#pragma unroll
    for (int j = 0; j < 4; j++) {
      int col = col0 + tx * 4 + j;
      float v = acc[i][j] + bias[col];
      if (col < 256) {
        int h = col >> 5, d2 = col & 31;
        d_K[(((size_t)bb * NH + h) * NNODE + n) * HDIM + d2] = v;
      } else if (col < 512) {
        int c = col - 256;
        int h = c >> 5, d2 = c & 31;
        d_V[(((size_t)bb * NH + h) * NNODE + n) * HDIM + d2] = v;
      } else {
        d_L[(size_t)m * DIM + (col - 512)] = v;
      }
    }
  }
}

// ---------------- per-step small GEMMs (M=512, N=256) ----------------
// mode 0: q = fixed + [ctx | ew_t] @ w_sc + b_sc          (K=768)
// mode 1: glimpse = heads @ w_out + b_out                 (K=256)
// mode 2: ctx += ([sel_emb | curr_emb] @ w_edge + b - ctx)/t   (K=512)
__global__ void k_smallgemm(int mode, int t,
                            const float* __restrict__ ne,
                            const float* __restrict__ ew,
                            const float* __restrict__ wmat,
                            const float* __restrict__ bias,
                            float tf) {
  __shared__ float As[16][72];
  __shared__ float Bs[16][64];
  int tid = threadIdx.x;
  int tx = tid & 15, ty = tid >> 4;
  int row0 = blockIdx.x * 64;
  int col0 = blockIdx.y * 64;
  int ar = tid >> 2, ac4 = tid & 3;
  int br = tid >> 4, bc4 = tid & 15;
  int K = (mode == 0) ? 768 : ((mode == 1) ? 256 : 512);
  float acc[4][4];
#pragma unroll
  for (int i = 0; i < 4; i++)
#pragma unroll
    for (int j = 0; j < 4; j++) acc[i][j] = 0.f;

  for (int k0 = 0; k0 < K; k0 += 16) {
    int m = row0 + ar;
    int kk = k0 + ac4 * 4;
    float4 av;
    if (mode == 0) {
      if (kk < 256)
        av = *(const float4*)&d_ctx[m * DIM + kk];
      else
        av = *(const float4*)&ew[((size_t)m * TSTEPS + t) * EWD + (kk - 256)];
    } else if (mode == 1) {
      av = *(const float4*)&d_heads[m * DIM + kk];
    } else {
      if (kk < 256) {
        int s = d_sel[m];
        av = *(const float4*)&ne[((size_t)m * NNODE + s) * DIM + kk];
      } else {
        av = *(const float4*)&ne[((size_t)m * NNODE + (NNODE - 1)) * DIM + (kk - 256)];
      }
    }
    As[ac4 * 4 + 0][ar] = av.x;
    As[ac4 * 4 + 1][ar] = av.y;
    As[ac4 * 4 + 2][ar] = av.z;
    As[ac4 * 4 + 3][ar] = av.w;
    *(float4*)&Bs[br][bc4 * 4] =
        *(const float4*)&wmat[(size_t)(k0 + br) * DIM + col0 + bc4 * 4];
    __syncthreads();
#pragma unroll
    for (int k = 0; k < 16; k++) {
      float4 a = *(const float4*)&As[k][ty * 4];
      float4 bv = *(const float4*)&Bs[k][tx * 4];
      float am[4] = {a.x, a.y, a.z, a.w};
      float bm[4] = {bv.x, bv.y, bv.z, bv.w};
#pragma unroll
      for (int i = 0; i < 4; i++)
#pragma unroll
        for (int j = 0; j < 4; j++) acc[i][j] += am[i] * bm[j];
    }
    __syncthreads();
  }
#pragma unroll
  for (int i = 0; i < 4; i++) {
    int m = row0 + ty * 4 + i;
#pragma unroll
    for (int j = 0; j < 4; j++) {
      int col = col0 + tx * 4 + j;
      float v = acc[i][j] + bias[col];
      if (mode == 0) {
        d_q[m * DIM + col] = v + d_fixed[m * DIM + col];
      } else if (mode == 1) {
        d_glimpse[m * DIM + col] = v;
      } else {
        float old = d_ctx[m * DIM + col];
        d_ctx[m * DIM + col] = old + (v - old) / tf;
      }
    }
  }
}

// ---------------- per-step attention: compat -> softmax -> heads ----------------
__global__ void k_attn() {
  int bh = blockIdx.x;                 // 4096 = B*H
  int b = bh >> 3, h = bh & 7;
  int tid = threadIdx.x, lane = tid & 31, w = tid >> 5;   // 8 warps
  __shared__ float sl[NNODE];
  __shared__ float red[8][32];
  __shared__ float rmax[8];
  __shared__ float rsum[8];

  float qv = d_q[(size_t)b * DIM + h * HDIM + lane];
  const float* Kb = &d_K[((size_t)(b * NH + h)) * NNODE * HDIM];
  const unsigned char* mk = &d_mask[(size_t)b * NNODE];

  for (int n = w; n < NNODE; n += 8) {
    float x = Kb[(size_t)n * HDIM + lane] * qv;
#pragma unroll
    for (int o = 16; o; o >>= 1) x += __shfl_xor_sync(0xffffffffu, x, o);
    if (lane == 0) sl[n] = mk[n] ? NEGV : x * INV_HD;
  }
  __syncthreads();

  // block max
  float m = -3.402823466e38f;
  for (int i = tid; i < NNODE; i += 256) m = fmaxf(m, sl[i]);
#pragma unroll
  for (int o = 16; o; o >>= 1) m = fmaxf(m, __shfl_xor_sync(0xffffffffu, m, o));
  if (lane == 0) rmax[w] = m;
  __syncthreads();
  float mm = rmax[0];
#pragma unroll
  for (int i = 1; i < 8; i++) mm = fmaxf(mm, rmax[i]);

  // exp + sum
  float s = 0.f;
  for (int i = tid; i < NNODE; i += 256) {
    float e = expf(sl[i] - mm);
    sl[i] = e;
    s += e;
  }
#pragma unroll
  for (int o = 16; o; o >>= 1) s += __shfl_xor_sync(0xffffffffu, s, o);
  if (lane == 0) rsum[w] = s;
  __syncthreads();
  float ss = rsum[0];
#pragma unroll
  for (int i = 1; i < 8; i++) ss += rsum[i];
  float rs = 1.0f / ss;
  for (int i = tid; i < NNODE; i += 256) sl[i] *= rs;
  __syncthreads();

  // heads = attn @ V
  const float* Vb = &d_V[((size_t)(b * NH + h)) * NNODE * HDIM];
  float acc = 0.f;
  for (int n = w; n < NNODE; n += 8) acc += sl[n] * Vb[(size_t)n * HDIM + lane];
  red[w][lane] = acc;
  __syncthreads();
  if (w == 0) {
    float a = 0.f;
#pragma unroll
    for (int i = 0; i < 8; i++) a += red[i][lane];
    d_heads[(size_t)b * DIM + h * HDIM + lane] = a;
  }
}

// ---------------- per-step logits + log_softmax + argmax + output ----------------
__global__ void k_logits(float* __restrict__ out, int t) {
  int b = blockIdx.x;                  // 512 blocks
  int tid = threadIdx.x, lane = tid & 31, w = tid >> 5;
  __shared__ float sl[NNODE];
  __shared__ float rmax[8];
  __shared__ int rid[8];
  __shared__ float rsum[8];

  const float* gb = &d_glimpse[(size_t)b * DIM];
  float4 g0 = *(const float4*)&gb[lane * 8];
  float4 g1 = *(const float4*)&gb[lane * 8 + 4];
  const float* Lb = &d_L[(size_t)b * NNODE * DIM];
  const unsigned char* mk = &d_mask[(size_t)b * NNODE];

  for (int n = w; n < NNODE; n += 8) {
    const float* row = Lb + (size_t)n * DIM + lane * 8;
    float4 r0 = *(const float4*)row;
    float4 r1 = *(const float4*)(row + 4);
    float x = r0.x * g0.x + r0.y * g0.y + r0.z * g0.z + r0.w * g0.w +
              r1.x * g1.x + r1.y * g1.y + r1.z * g1.z + r1.w * g1.w;
#pragma unroll
    for (int o = 16; o; o >>= 1) x += __shfl_xor_sync(0xffffffffu, x, o);
    if (lane == 0) {
      float l = tanh10(x * INV_D);
      sl[n] = mk[n] ? NEGV : l;
    }
  }
  __syncthreads();

  // block max + argmax (first occurrence on ties)
  float m = -3.402823466e38f;
  int mi = NNODE;
  for (int i = tid; i < NNODE; i += 256) {
    float v = sl[i];
    if (v > m) { m = v; mi = i; }
  }
#pragma unroll
  for (int o = 16; o; o >>= 1) {
    float om = __shfl_xor_sync(0xffffffffu, m, o);
    int oi = __shfl_xor_sync(0xffffffffu, mi, o);
    if (om > m || (om == m && oi < mi)) { m = om; mi = oi; }
  }
  if (lane == 0) { rmax[w] = m; rid[w] = mi; }
  __syncthreads();
  float mm = rmax[0];
  int bi = rid[0];
#pragma unroll
  for (int i = 1; i < 8; i++) {
    if (rmax[i] > mm || (rmax[i] == mm && rid[i] < bi)) { mm = rmax[i]; bi = rid[i]; }
  }

  // sum exp
  float s = 0.f;
  for (int i = tid; i < NNODE; i += 256) s += expf(sl[i] - mm);
#pragma unroll
  for (int o = 16; o; o >>= 1) s += __shfl_xor_sync(0xffffffffu, s, o);
  if (lane == 0) rsum[w] = s;
  __syncthreads();
  float ss = rsum[0];
#pragma unroll
  for (int i = 1; i < 8; i++) ss += rsum[i];
  float lse = mm + logf(ss);

  float* ob = out + ((size_t)b * TSTEPS + t) * NNODE;
  for (int i = tid; i < NNODE; i += 256) ob[i] = sl[i] - lse;
  if (tid == 0) {
    d_sel[b] = bi;
    if (bi > 0) d_mask[(size_t)b * NNODE + bi] = 1;
  }
}

// ---------------- launch ----------------
extern "C" void kernel_launch(void* const* d_in, const int* in_sizes, int n_in,
                              void* d_out, int out_size) {
  const float* ne     = (const float*)d_in[0];   // (B, N, D)
  const float* ew     = (const float*)d_in[1];   // (B, T, U+1)
  const float* w_kvl  = (const float*)d_in[2];   // (D, 3D)
  const float* b_kvl  = (const float*)d_in[3];
  const float* w_fc   = (const float*)d_in[4];   // (D, D)
  const float* b_fc   = (const float*)d_in[5];
  const float* w_sc   = (const float*)d_in[6];   // (768, D)
  const float* b_sc   = (const float*)d_in[7];
  const float* w_out  = (const float*)d_in[8];   // (D, D)
  const float* b_out  = (const float*)d_in[9];
  const float* w_edge = (const float*)d_in[10];  // (2D, D)
  const float* b_edge = (const float*)d_in[11];
  float* out = (float*)d_out;

  k_precompute_fixed<<<BATCH, 256>>>(ne, w_fc, b_fc);
  k_kvl<<<dim3((BATCH * NNODE) / 64, 768 / 64), 256>>>(ne, w_kvl, b_kvl);

  for (int t = 0; t < TSTEPS; ++t) {
    k_smallgemm<<<dim3(8, 4), 256>>>(0, t, ne, ew, w_sc, b_sc, 0.f);
    k_attn<<<BATCH * NH, 256>>>();
    k_smallgemm<<<dim3(8, 4), 256>>>(1, t, ne, ew, w_out, b_out, 0.f);
    k_logits<<<BATCH, 256>>>(out, t);
    k_smallgemm<<<dim3(8, 4), 256>>>(2, t, ne, ew, w_edge, b_edge, (float)(t + 1));
  }
}

// round 4
// speedup vs baseline: 1.0782x; 1.0782x over previous
#include <cuda_runtime.h>
#include <math.h>

#define BATCH 512
#define NNODE 513
#define NPAD  520          // padded node stride (16B-aligned rows)
#define DIM   256
#define NH    8
#define HDIM  32
#define TSTEPS 128
#define EWD   512          // U+1
#define NEGV  -1000000000.0f
#define INV_HD 0.176776695296636893f   // 1/sqrt(32)
#define INV_D  0.0625f                 // 1/sqrt(256)

// ---------------- static device scratch (no allocations allowed) ----------------
// Transposed layouts: K,V = (b, h, d, n_pad)   L = (b, d, n_pad)
static __device__ float d_K[(size_t)BATCH * NH * HDIM * NPAD];
static __device__ float d_V[(size_t)BATCH * NH * HDIM * NPAD];
static __device__ float d_L[(size_t)BATCH * DIM * NPAD];
static __device__ float d_fixed[BATCH * DIM];
static __device__ float d_ctx[BATCH * DIM];
static __device__ float d_q[BATCH * DIM];
static __device__ unsigned char d_mask[BATCH * NNODE];
static __device__ int d_sel[BATCH];

// 10*tanh(x) built from expf so fast-math __tanhf (2^-11 err) can't perturb argmax.
__device__ __forceinline__ float tanh10(float x) {
  float ax = fabsf(x);
  float t = expf(-2.0f * ax);
  float r = (1.0f - t) / (1.0f + t);
  return copysignf(10.0f * r, x);
}

// ---------------- precompute: graph mean -> fixed_ctx; init state ----------------
__global__ void k_precompute_fixed(const float* __restrict__ ne,
                                   const float* __restrict__ w_fc,
                                   const float* __restrict__ b_fc) {
  int b = blockIdx.x, tid = threadIdx.x;
  __shared__ float mean[DIM];
  const float* base = ne + (size_t)b * NNODE * DIM;
  float acc = 0.f;
  for (int n = 0; n < NNODE; ++n) acc += base[(size_t)n * DIM + tid];
  mean[tid] = acc / (float)NNODE;
  __syncthreads();
  float o = b_fc[tid];
  for (int d = 0; d < DIM; ++d) o += mean[d] * w_fc[d * DIM + tid];
  d_fixed[b * DIM + tid] = o;
  d_ctx[b * DIM + tid] = 0.f;
  for (int i = tid; i < NNODE; i += 256) d_mask[(size_t)b * NNODE + i] = 0;
}

// ---------------- precompute: KVL = node_embeds @ w_kvl + b, scattered transposed ----------------
// M = BATCH*NNODE = 262656, K = 256, N = 768.  64x64 tiles, BK=16, 4x4 per thread.
__global__ void k_kvl(const float* __restrict__ ne,
                      const float* __restrict__ w,
                      const float* __restrict__ bias) {
  __shared__ float As[16][72];
  __shared__ float Bs[16][64];
  int tid = threadIdx.x;
  int tx = tid & 15, ty = tid >> 4;
  int row0 = blockIdx.x * 64;
  int col0 = blockIdx.y * 64;
  int ar = tid >> 2, ac4 = tid & 3;
  int br = tid >> 4, bc4 = tid & 15;
  float acc[4][4];
#pragma unroll
  for (int i = 0; i < 4; i++)
#pragma unroll
    for (int j = 0; j < 4; j++) acc[i][j] = 0.f;

  for (int k0 = 0; k0 < DIM; k0 += 16) {
    float4 av = *(const float4*)&ne[(size_t)(row0 + ar) * DIM + k0 + ac4 * 4];
    As[ac4 * 4 + 0][ar] = av.x;
    As[ac4 * 4 + 1][ar] = av.y;
    As[ac4 * 4 + 2][ar] = av.z;
    As[ac4 * 4 + 3][ar] = av.w;
    *(float4*)&Bs[br][bc4 * 4] =
        *(const float4*)&w[(size_t)(k0 + br) * 768 + col0 + bc4 * 4];
    __syncthreads();
#pragma unroll
    for (int k = 0; k < 16; k++) {
      float4 a = *(const float4*)&As[k][ty * 4];
      float4 bv = *(const float4*)&Bs[k][tx * 4];
      float am[4] = {a.x, a.y, a.z, a.w};
      float bm[4] = {bv.x, bv.y, bv.z, bv.w};
#pragma unroll
      for (int i = 0; i < 4; i++)
#pragma unroll
        for (int j = 0; j < 4; j++) acc[i][j] += am[i] * bm[j];
    }
    __syncthreads();
  }
#pragma unroll
  for (int i = 0; i < 4; i++) {
    int m = row0 + ty * 4 + i;
    int bb = m / NNODE;
    int n = m - bb * NNODE;
#pragma unroll
    for (int j = 0; j < 4; j++) {
      int col = col0 + tx * 4 + j;
      float v = acc[i][j] + bias[col];
      if (col < 256) {
        int h = col >> 5, dd = col & 31;
        d_K[(((size_t)bb * NH + h) * HDIM + dd) * NPAD + n] = v;
      } else if (col < 512) {
        int c = col - 256;
        int h = c >> 5, dd = c & 31;
        d_V[(((size_t)bb * NH + h) * HDIM + dd) * NPAD + n] = v;
      } else {
        d_L[((size_t)bb * DIM + (col - 512)) * NPAD + n] = v;
      }
    }
  }
}

// ---------------- per-step small GEMMs (M=512, N=256) ----------------
// mode 0: q = fixed + [ctx | ew_t] @ w_sc + b_sc          (K=768)
// mode 2: ctx += ([sel_emb | curr_emb] @ w_edge + b - ctx)/t   (K=512)
__global__ void k_smallgemm(int mode, int t,
                            const float* __restrict__ ne,
                            const float* __restrict__ ew,
                            const float* __restrict__ wmat,
                            const float* __restrict__ bias,
                            float tf) {
  __shared__ float As[16][72];
  __shared__ float Bs[16][64];
  int tid = threadIdx.x;
  int tx = tid & 15, ty = tid >> 4;
  int row0 = blockIdx.x * 64;
  int col0 = blockIdx.y * 64;
  int ar = tid >> 2, ac4 = tid & 3;
  int br = tid >> 4, bc4 = tid & 15;
  int K = (mode == 0) ? 768 : 512;
  float acc[4][4];
#pragma unroll
  for (int i = 0; i < 4; i++)
#pragma unroll
    for (int j = 0; j < 4; j++) acc[i][j] = 0.f;

  for (int k0 = 0; k0 < K; k0 += 16) {
    int m = row0 + ar;
    int kk = k0 + ac4 * 4;
    float4 av;
    if (mode == 0) {
      if (kk < 256)
        av = *(const float4*)&d_ctx[m * DIM + kk];
      else
        av = *(const float4*)&ew[((size_t)m * TSTEPS + t) * EWD + (kk - 256)];
    } else {
      if (kk < 256) {
        int s = d_sel[m];
        av = *(const float4*)&ne[((size_t)m * NNODE + s) * DIM + kk];
      } else {
        av = *(const float4*)&ne[((size_t)m * NNODE + (NNODE - 1)) * DIM + (kk - 256)];
      }
    }
    As[ac4 * 4 + 0][ar] = av.x;
    As[ac4 * 4 + 1][ar] = av.y;
    As[ac4 * 4 + 2][ar] = av.z;
    As[ac4 * 4 + 3][ar] = av.w;
    *(float4*)&Bs[br][bc4 * 4] =
        *(const float4*)&wmat[(size_t)(k0 + br) * DIM + col0 + bc4 * 4];
    __syncthreads();
#pragma unroll
    for (int k = 0; k < 16; k++) {
      float4 a = *(const float4*)&As[k][ty * 4];
      float4 bv = *(const float4*)&Bs[k][tx * 4];
      float am[4] = {a.x, a.y, a.z, a.w};
      float bm[4] = {bv.x, bv.y, bv.z, bv.w};
#pragma unroll
      for (int i = 0; i < 4; i++)
#pragma unroll
        for (int j = 0; j < 4; j++) acc[i][j] += am[i] * bm[j];
    }
    __syncthreads();
  }
#pragma unroll
  for (int i = 0; i < 4; i++) {
    int m = row0 + ty * 4 + i;
#pragma unroll
    for (int j = 0; j < 4; j++) {
      int col = col0 + tx * 4 + j;
      float v = acc[i][j] + bias[col];
      if (mode == 0) {
        d_q[m * DIM + col] = v + d_fixed[m * DIM + col];
      } else {
        float old = d_ctx[m * DIM + col];
        d_ctx[m * DIM + col] = old + (v - old) / tf;
      }
    }
  }
}

// ---------------- fused per-step mega kernel: one block per batch element ----------------
// attention (8 heads) -> glimpse matvec -> logits -> log_softmax -> argmax -> mask update
__global__ __launch_bounds__(256) void k_step(float* __restrict__ out,
                                              const float* __restrict__ w_out,
                                              const float* __restrict__ b_out,
                                              int t) {
  int b = blockIdx.x;
  int tid = threadIdx.x, lane = tid & 31, w = tid >> 5;
  __shared__ float s_q[DIM];
  __shared__ float s_at[NH][NPAD];   // compat -> attn weights per head
  __shared__ float s_heads[DIM];
  __shared__ float s_g[DIM];
  __shared__ float s_l[NNODE];
  __shared__ unsigned char s_mask[NNODE];
  __shared__ float s_rm[8];
  __shared__ int s_ri[8];
  __shared__ float s_rs[8];

  s_q[tid] = d_q[b * DIM + tid];
  for (int i = tid; i < NNODE; i += 256) s_mask[i] = d_mask[(size_t)b * NNODE + i];
  __syncthreads();

  // ---- compat: thread owns nodes {tid, tid+256, (512 if tid==0)} ----
  const float* Kb = d_K + (size_t)b * NH * HDIM * NPAD;
  for (int h = 0; h < NH; ++h) {
    const float* Kh = Kb + (size_t)h * HDIM * NPAD;
    float a0 = 0.f, a1 = 0.f, a2 = 0.f;
#pragma unroll
    for (int d = 0; d < HDIM; ++d) {
      float qv = s_q[h * HDIM + d];
      const float* row = Kh + (size_t)d * NPAD;
      a0 = fmaf(row[tid], qv, a0);
      a1 = fmaf(row[tid + 256], qv, a1);
      if (tid == 0) a2 = fmaf(row[512], qv, a2);
    }
    s_at[h][tid]       = s_mask[tid]       ? NEGV : a0 * INV_HD;
    s_at[h][tid + 256] = s_mask[tid + 256] ? NEGV : a1 * INV_HD;
    if (tid == 0) s_at[h][512] = s_mask[512] ? NEGV : a2 * INV_HD;
  }
  __syncthreads();

  // ---- softmax per head: warp w handles head h = w ----
  {
    float m = -3.402823466e38f;
    for (int i = lane; i < NNODE; i += 32) m = fmaxf(m, s_at[w][i]);
#pragma unroll
    for (int o = 16; o; o >>= 1) m = fmaxf(m, __shfl_xor_sync(0xffffffffu, m, o));
    float s = 0.f;
    for (int i = lane; i < NNODE; i += 32) {
      float e = expf(s_at[w][i] - m);
      s_at[w][i] = e;
      s += e;
    }
#pragma unroll
    for (int o = 16; o; o >>= 1) s += __shfl_xor_sync(0xffffffffu, s, o);
    float inv = 1.0f / s;
    for (int i = lane; i < NNODE; i += 32) s_at[w][i] *= inv;
  }
  __syncthreads();

  // ---- heads: warp w computes head h=w, all 32 dims ----
  {
    const float* Vh = d_V + ((size_t)b * NH + w) * HDIM * NPAD;
    for (int j = 0; j < HDIM; ++j) {
      const float* row = Vh + (size_t)j * NPAD;
      float acc = 0.f;
      for (int i = lane; i < NNODE; i += 32) acc += s_at[w][i] * row[i];
#pragma unroll
      for (int o = 16; o; o >>= 1) acc += __shfl_xor_sync(0xffffffffu, acc, o);
      if (lane == 0) s_heads[w * HDIM + j] = acc;
    }
  }
  __syncthreads();

  // ---- glimpse = heads @ w_out + b_out (w_out is L2-hot across blocks) ----
  {
    float g = b_out[tid];
#pragma unroll 8
    for (int d = 0; d < DIM; ++d) g = fmaf(s_heads[d], w_out[d * DIM + tid], g);
    s_g[tid] = g;
  }
  __syncthreads();

  // ---- logits = tanh10(glimpse . L_n / 16), masked ----
  {
    const float* Lb = d_L + (size_t)b * DIM * NPAD;
    float a0 = 0.f, a1 = 0.f, a2 = 0.f;
#pragma unroll 8
    for (int d = 0; d < DIM; ++d) {
      float g = s_g[d];
      const float* row = Lb + (size_t)d * NPAD;
      a0 = fmaf(row[tid], g, a0);
      a1 = fmaf(row[tid + 256], g, a1);
      if (tid == 0) a2 = fmaf(row[512], g, a2);
    }
    s_l[tid]       = s_mask[tid]       ? NEGV : tanh10(a0 * INV_D);
    s_l[tid + 256] = s_mask[tid + 256] ? NEGV : tanh10(a1 * INV_D);
    if (tid == 0) s_l[512] = s_mask[512] ? NEGV : tanh10(a2 * INV_D);
  }
  __syncthreads();

  // ---- argmax (first occurrence on ties) ----
  float m = -3.402823466e38f;
  int mi = NNODE;
  for (int i = tid; i < NNODE; i += 256) {
    float v = s_l[i];
    if (v > m) { m = v; mi = i; }
  }
#pragma unroll
  for (int o = 16; o; o >>= 1) {
    float om = __shfl_xor_sync(0xffffffffu, m, o);
    int oi = __shfl_xor_sync(0xffffffffu, mi, o);
    if (om > m || (om == m && oi < mi)) { m = om; mi = oi; }
  }
  if (lane == 0) { s_rm[w] = m; s_ri[w] = mi; }
  __syncthreads();
  float mm = s_rm[0];
  int bi = s_ri[0];
#pragma unroll
  for (int i = 1; i < 8; i++) {
    if (s_rm[i] > mm || (s_rm[i] == mm && s_ri[i] < bi)) { mm = s_rm[i]; bi = s_ri[i]; }
  }

  // ---- logsumexp ----
  float s = 0.f;
  for (int i = tid; i < NNODE; i += 256) s += expf(s_l[i] - mm);
#pragma unroll
  for (int o = 16; o; o >>= 1) s += __shfl_xor_sync(0xffffffffu, s, o);
  if (lane == 0) s_rs[w] = s;
  __syncthreads();
  float ss = s_rs[0];
#pragma unroll
  for (int i = 1; i < 8; i++) ss += s_rs[i];
  float lse = mm + logf(ss);

  float* ob = out + ((size_t)b * TSTEPS + t) * NNODE;
  for (int i = tid; i < NNODE; i += 256) ob[i] = s_l[i] - lse;
  if (tid == 0) {
    d_sel[b] = bi;
    if (bi > 0) d_mask[(size_t)b * NNODE + bi] = 1;
  }
}

// ---------------- launch ----------------
extern "C" void kernel_launch(void* const* d_in, const int* in_sizes, int n_in,
                              void* d_out, int out_size) {
  const float* ne     = (const float*)d_in[0];   // (B, N, D)
  const float* ew     = (const float*)d_in[1];   // (B, T, U+1)
  const float* w_kvl  = (const float*)d_in[2];   // (D, 3D)
  const float* b_kvl  = (const float*)d_in[3];
  const float* w_fc   = (const float*)d_in[4];   // (D, D)
  const float* b_fc   = (const float*)d_in[5];
  const float* w_sc   = (const float*)d_in[6];   // (768, D)
  const float* b_sc   = (const float*)d_in[7];
  const float* w_out  = (const float*)d_in[8];   // (D, D)
  const float* b_out  = (const float*)d_in[9];
  const float* w_edge = (const float*)d_in[10];  // (2D, D)
  const float* b_edge = (const float*)d_in[11];
  float* out = (float*)d_out;

  k_precompute_fixed<<<BATCH, 256>>>(ne, w_fc, b_fc);
  k_kvl<<<dim3((BATCH * NNODE) / 64, 768 / 64), 256>>>(ne, w_kvl, b_kvl);

  for (int t = 0; t < TSTEPS; ++t) {
    k_smallgemm<<<dim3(8, 4), 256>>>(0, t, ne, ew, w_sc, b_sc, 0.f);
    k_step<<<BATCH, 256>>>(out, w_out, b_out, t);
    k_smallgemm<<<dim3(8, 4), 256>>>(2, t, ne, ew, w_edge, b_edge, (float)(t + 1));
  }
}